// round 10
// baseline (speedup 1.0000x reference)
#include <cuda_runtime.h>
#include <cuda_bf16.h>
#include <cstdint>

#define T_LEN    2048
#define D_DIM    128
#define NQ_H     32
#define NKV_H    8
#define B_MAX    2
#define BM       64
#define BN       32
#define NTHREADS 128
#define LOG2E    1.4426950408889634f

// smem (bytes): bf16 tiles, row stride 272B -> conflict-free ldmatrix
#define ROWB     272
#define QSUBSZ   17408          // 64 rows
#define KSUBSZ   8704           // 32 rows
#define OFF_QHI  0
#define OFF_QLO  17408
#define OFF_KV   34816          // 2 buffers x (KHI,KLO,VHI,VLO) x 8704
#define BUFSZ    34816
#define OFF_SEG  104448         // 2 x 128 B
#define SMEM_TOTAL 104704

// pre-split K/V scratch (bf16 hi/lo), layout [b][kvh][t][d]
#define KV_ELEMS (B_MAX * NKV_H * T_LEN * D_DIM)
__device__ __nv_bfloat16 g_khi[KV_ELEMS];
__device__ __nv_bfloat16 g_klo[KV_ELEMS];
__device__ __nv_bfloat16 g_vhi[KV_ELEMS];
__device__ __nv_bfloat16 g_vlo[KV_ELEMS];

__device__ __forceinline__ uint32_t smem_u32(const void* p) {
    uint32_t a;
    asm("{ .reg .u64 t; cvta.to.shared.u64 t, %1; cvt.u32.u64 %0, t; }" : "=r"(a) : "l"(p));
    return a;
}
__device__ __forceinline__ float ex2f(float x) {
    float r;
    asm("ex2.approx.ftz.f32 %0, %1;" : "=f"(r) : "f"(x));
    return r;
}
__device__ __forceinline__ void mma16816(float* d, const uint32_t* a, const uint32_t* b) {
    asm volatile("mma.sync.aligned.m16n8k16.row.col.f32.bf16.bf16.f32 "
                 "{%0,%1,%2,%3}, {%4,%5,%6,%7}, {%8,%9}, {%0,%1,%2,%3};"
                 : "+f"(d[0]), "+f"(d[1]), "+f"(d[2]), "+f"(d[3])
                 : "r"(a[0]), "r"(a[1]), "r"(a[2]), "r"(a[3]), "r"(b[0]), "r"(b[1]));
}
__device__ __forceinline__ void ldsm_x4(uint32_t* r, uint32_t addr) {
    asm volatile("ldmatrix.sync.aligned.m8n8.x4.shared.b16 {%0,%1,%2,%3}, [%4];"
                 : "=r"(r[0]), "=r"(r[1]), "=r"(r[2]), "=r"(r[3]) : "r"(addr));
}
__device__ __forceinline__ void ldsm_x4t(uint32_t* r, uint32_t addr) {
    asm volatile("ldmatrix.sync.aligned.m8n8.x4.trans.shared.b16 {%0,%1,%2,%3}, [%4];"
                 : "=r"(r[0]), "=r"(r[1]), "=r"(r[2]), "=r"(r[3]) : "r"(addr));
}
__device__ __forceinline__ void split2(float x, float y, uint32_t& hi, uint32_t& lo) {
    __nv_bfloat162 h = __floats2bfloat162_rn(x, y);
    float hx = __low2float(h), hy = __high2float(h);
    __nv_bfloat162 l = __floats2bfloat162_rn(x - hx, y - hy);
    hi = *(uint32_t*)&h;
    lo = *(uint32_t*)&l;
}
__device__ __forceinline__ void cp16(uint32_t dst, const void* src) {
    size_t g = __cvta_generic_to_global(src);
    asm volatile("cp.async.cg.shared.global [%0], [%1], 16;" :: "r"(dst), "l"(g) : "memory");
}
#define CP_COMMIT() asm volatile("cp.async.commit_group;" ::: "memory")
#define CP_WAIT0()  asm volatile("cp.async.wait_group 0;" ::: "memory")

// ---- prep kernel: split K/V f32 -> bf16 hi/lo, relayout [b][kvh][t][d] ----
__global__ void prep_kv(const float* __restrict__ K, const float* __restrict__ V) {
    const int t = blockIdx.x, h = blockIdx.y, b = blockIdx.z;
    const int d = threadIdx.x * 2;
    const size_t src = ((size_t)(b * T_LEN + t) * NKV_H + h) * D_DIM + d;
    const size_t dst = ((size_t)(b * NKV_H + h) * T_LEN + t) * D_DIM + d;
    float2 kv = *(const float2*)(K + src);
    float2 vv = *(const float2*)(V + src);
    uint32_t hh, ll;
    split2(kv.x, kv.y, hh, ll);
    *(uint32_t*)(g_khi + dst) = hh; *(uint32_t*)(g_klo + dst) = ll;
    split2(vv.x, vv.y, hh, ll);
    *(uint32_t*)(g_vhi + dst) = hh; *(uint32_t*)(g_vlo + dst) = ll;
}

__device__ __forceinline__ void prefetch_tile(uint32_t sb, int buf, int tid,
                                              size_t kvoff, int n0,
                                              const int* __restrict__ segB) {
    const uint32_t base = sb + OFF_KV + buf * BUFSZ;
    const __nv_bfloat16* srcs[4] = { g_khi + kvoff, g_klo + kvoff,
                                     g_vhi + kvoff, g_vlo + kvoff };
#pragma unroll
    for (int sub = 0; sub < 4; sub++) {
        const __nv_bfloat16* sp = srcs[sub] + (size_t)n0 * D_DIM;
#pragma unroll
        for (int q = 0; q < 4; q++) {
            const int i = tid + q * NTHREADS;
            const int row = i >> 4, ch = i & 15;
            cp16(base + sub * KSUBSZ + row * ROWB + ch * 16,
                 sp + row * D_DIM + ch * 8);
        }
    }
    if (tid < 8) cp16(sb + OFF_SEG + buf * 128 + tid * 16, segB + n0 + tid * 4);
}

__global__ __launch_bounds__(NTHREADS, 2)
void attn_fwd_mma(const float* __restrict__ Q, const int* __restrict__ SEG,
                  float* __restrict__ O)
{
    extern __shared__ __align__(16) char smem[];
    const uint32_t sb = smem_u32(smem);

    const int b   = blockIdx.z;
    const int qh  = blockIdx.y;
    const int kvh = qh >> 2;
    const int m0  = ((int)gridDim.x - 1 - (int)blockIdx.x) * BM;  // heavy blocks first

    const int tid  = threadIdx.x;
    const int w    = tid >> 5;        // 0..3
    const int lane = tid & 31;
    const int g    = lane >> 2;
    const int qc   = lane & 3;

    const int* segB = SEG + b * T_LEN;
    const size_t kvoff = ((size_t)b * NKV_H + kvh) * T_LEN * D_DIM;

    // ---- load Q tile [BM x D], scale by log2e, split hi/lo ----
    const float* qbase = Q + ((size_t)(b * T_LEN + m0) * NQ_H + qh) * D_DIM;
    for (int i = tid; i < BM * (D_DIM / 4); i += NTHREADS) {
        int r = i >> 5, e = (i & 31) * 4;
        float4 qv = *(const float4*)(qbase + (size_t)r * NQ_H * D_DIM + e);
        uint32_t h0, l0, h1, l1;
        split2(qv.x * LOG2E, qv.y * LOG2E, h0, l0);
        split2(qv.z * LOG2E, qv.w * LOG2E, h1, l1);
        uint32_t off = (uint32_t)(r * ROWB + e * 2);
        *(uint32_t*)(smem + OFF_QHI + off)     = h0;
        *(uint32_t*)(smem + OFF_QHI + off + 4) = h1;
        *(uint32_t*)(smem + OFF_QLO + off)     = l0;
        *(uint32_t*)(smem + OFF_QLO + off + 4) = l1;
    }

    const int rG0 = m0 + w * 16 + g;
    const int rG1 = rG0 + 8;
    const int segRowMin = segB[m0];
    const int segRowMax = segB[m0 + BM - 1];
    const int rowSeg0 = segB[rG0];
    const int rowSeg1 = segB[rG1];

    float m0r = -1e30f, m1r = -1e30f, l0r = 0.f, l1r = 0.f;
    float o[16][4];
#pragma unroll
    for (int j = 0; j < 16; j++)
#pragma unroll
        for (int u = 0; u < 4; u++) o[j][u] = 0.f;

    // ldmatrix lane address components
    const int arow = w * 16 + (lane & 7) + ((lane >> 3) & 1) * 8;
    const uint32_t aColOff = (uint32_t)(((lane >> 4) * 8) * 2);
    const uint32_t aHiBase = sb + OFF_QHI + (uint32_t)arow * ROWB + aColOff;
    const uint32_t aLoBase = sb + OFF_QLO + (uint32_t)arow * ROWB + aColOff;
    const uint32_t bRow4 = (uint32_t)(((lane & 7) + ((lane >> 4) & 1) * 8) * ROWB
                                      + ((lane >> 3) & 1) * 16);
    const uint32_t vRow4 = (uint32_t)(((lane & 7) + ((lane >> 3) & 1) * 8) * ROWB
                                      + ((lane >> 4) & 1) * 16);

    const int nTiles = m0 / BN + 2;   // BM = 2*BN

    // ---- find first valid tile, start prefetch ----
    int ntCur = -1;
    for (int t = 0; t < nTiles; t++) {
        if (!(segB[t * BN] > segRowMax || segB[t * BN + BN - 1] < segRowMin)) { ntCur = t; break; }
    }
    int buf = 0;
    if (ntCur >= 0) { prefetch_tile(sb, buf, tid, kvoff, ntCur * BN, segB); CP_COMMIT(); }

    while (ntCur >= 0) {
        int ntNext = -1;
        for (int t = ntCur + 1; t < nTiles; t++) {
            if (!(segB[t * BN] > segRowMax || segB[t * BN + BN - 1] < segRowMin)) { ntNext = t; break; }
        }

        CP_WAIT0();
        __syncthreads();   // tile visible; all warps done with buf^1

        if (ntNext >= 0) { prefetch_tile(sb, buf ^ 1, tid, kvoff, ntNext * BN, segB); CP_COMMIT(); }

        const int n0 = ntCur * BN;
        const uint32_t bufBase = sb + OFF_KV + buf * BUFSZ;
        const int* segK = (const int*)(smem + OFF_SEG + buf * 128);

        // ---- S = Q K^T (3-term): 64x32 tile, warp owns 16 rows ----
        float s[4][4];
#pragma unroll
        for (int j = 0; j < 4; j++)
#pragma unroll
            for (int u = 0; u < 4; u++) s[j][u] = 0.f;

#pragma unroll
        for (int kc = 0; kc < 8; kc++) {
            uint32_t aHi[4], aLo[4];
            ldsm_x4(aHi, aHiBase + kc * 32);
            ldsm_x4(aLo, aLoBase + kc * 32);
#pragma unroll
            for (int jp = 0; jp < 2; jp++) {
                uint32_t bHi[4], bLo[4];
                const uint32_t bo = bufBase + (uint32_t)(jp * 16 * ROWB) + bRow4 + kc * 32;
                ldsm_x4(bHi, bo);
                ldsm_x4(bLo, bo + KSUBSZ);
                mma16816(s[2*jp],   aHi, bHi);
                mma16816(s[2*jp],   aHi, bLo);
                mma16816(s[2*jp],   aLo, bHi);
                mma16816(s[2*jp+1], aHi, bHi + 2);
                mma16816(s[2*jp+1], aHi, bLo + 2);
                mma16816(s[2*jp+1], aLo, bHi + 2);
            }
        }

        // ---- mask + online softmax (warp-local) ----
        float mt0 = -1e30f, mt1 = -1e30f;
#pragma unroll
        for (int j = 0; j < 4; j++) {
            const int col = 8 * j + 2 * qc;
            const int c0 = n0 + col, c1 = c0 + 1;
            const int sg0 = segK[col], sg1 = segK[col + 1];
            if (!(c0 <= rG0 && sg0 == rowSeg0)) s[j][0] = -1e30f;
            if (!(c1 <= rG0 && sg1 == rowSeg0)) s[j][1] = -1e30f;
            if (!(c0 <= rG1 && sg0 == rowSeg1)) s[j][2] = -1e30f;
            if (!(c1 <= rG1 && sg1 == rowSeg1)) s[j][3] = -1e30f;
            mt0 = fmaxf(mt0, fmaxf(s[j][0], s[j][1]));
            mt1 = fmaxf(mt1, fmaxf(s[j][2], s[j][3]));
        }
        mt0 = fmaxf(mt0, __shfl_xor_sync(0xffffffffu, mt0, 1));
        mt0 = fmaxf(mt0, __shfl_xor_sync(0xffffffffu, mt0, 2));
        mt1 = fmaxf(mt1, __shfl_xor_sync(0xffffffffu, mt1, 1));
        mt1 = fmaxf(mt1, __shfl_xor_sync(0xffffffffu, mt1, 2));

        const float mn0 = fmaxf(m0r, mt0), mn1 = fmaxf(m1r, mt1);
        const float al0 = ex2f(m0r - mn0), al1 = ex2f(m1r - mn1);
        m0r = mn0; m1r = mn1;

        float ls0 = 0.f, ls1 = 0.f;
#pragma unroll
        for (int j = 0; j < 4; j++) {
            s[j][0] = ex2f(s[j][0] - mn0);
            s[j][1] = ex2f(s[j][1] - mn0);
            s[j][2] = ex2f(s[j][2] - mn1);
            s[j][3] = ex2f(s[j][3] - mn1);
            ls0 += s[j][0] + s[j][1];
            ls1 += s[j][2] + s[j][3];
        }
        ls0 += __shfl_xor_sync(0xffffffffu, ls0, 1);
        ls0 += __shfl_xor_sync(0xffffffffu, ls0, 2);
        ls1 += __shfl_xor_sync(0xffffffffu, ls1, 1);
        ls1 += __shfl_xor_sync(0xffffffffu, ls1, 2);
        l0r = l0r * al0 + ls0;
        l1r = l1r * al1 + ls1;

        // ---- rescale O (skip if alpha==1 warp-wide) ----
        if (!__all_sync(0xffffffffu, (al0 == 1.f) && (al1 == 1.f))) {
#pragma unroll
            for (int j = 0; j < 16; j++) {
                o[j][0] *= al0; o[j][1] *= al0;
                o[j][2] *= al1; o[j][3] *= al1;
            }
        }

        // ---- O += P V : P 16x32 per warp, V 32x128 ----
        const uint32_t vBase = bufBase + 2 * KSUBSZ;
#pragma unroll
        for (int kc2 = 0; kc2 < 2; kc2++) {
            uint32_t pHi[4], pLo[4];
            split2(s[2*kc2][0],   s[2*kc2][1],   pHi[0], pLo[0]);
            split2(s[2*kc2][2],   s[2*kc2][3],   pHi[1], pLo[1]);
            split2(s[2*kc2+1][0], s[2*kc2+1][1], pHi[2], pLo[2]);
            split2(s[2*kc2+1][2], s[2*kc2+1][3], pHi[3], pLo[3]);
            const uint32_t vRowBase = vBase + (uint32_t)(kc2 * 16 * ROWB) + vRow4;
#pragma unroll
            for (int j2p = 0; j2p < 8; j2p++) {
                uint32_t vHi[4], vLo[4];
                const uint32_t bo = vRowBase + j2p * 32;
                ldsm_x4t(vHi, bo);
                ldsm_x4t(vLo, bo + KSUBSZ);
                mma16816(o[2*j2p],   pHi, vHi);
                mma16816(o[2*j2p],   pHi, vLo);
                mma16816(o[2*j2p],   pLo, vHi);
                mma16816(o[2*j2p+1], pHi, vHi + 2);
                mma16816(o[2*j2p+1], pHi, vLo + 2);
                mma16816(o[2*j2p+1], pLo, vHi + 2);
            }
        }

        buf ^= 1;
        ntCur = ntNext;
    }

    // ---- epilogue ----
    {
        const float i0 = 1.0f / l0r, i1 = 1.0f / l1r;
        float* ob0 = O + ((size_t)(b * T_LEN + rG0) * NQ_H + qh) * D_DIM;
        float* ob1 = O + ((size_t)(b * T_LEN + rG1) * NQ_H + qh) * D_DIM;
#pragma unroll
        for (int j2 = 0; j2 < 16; j2++) {
            const int col = 8 * j2 + 2 * qc;
            *(float2*)(ob0 + col) = make_float2(o[j2][0] * i0, o[j2][1] * i0);
            *(float2*)(ob1 + col) = make_float2(o[j2][2] * i1, o[j2][3] * i1);
        }
    }
}

extern "C" void kernel_launch(void* const* d_in, const int* in_sizes, int n_in,
                              void* d_out, int out_size)
{
    const float* q   = (const float*)d_in[0];
    const float* k   = (const float*)d_in[1];
    const float* v   = (const float*)d_in[2];
    const int*   seg = (const int*)d_in[3];
    float*       out = (float*)d_out;

    const int B = in_sizes[0] / (T_LEN * NQ_H * D_DIM);

    dim3 pgrid(T_LEN, NKV_H, B);
    prep_kv<<<pgrid, 64>>>(k, v);

    cudaFuncSetAttribute(attn_fwd_mma, cudaFuncAttributeMaxDynamicSharedMemorySize, SMEM_TOTAL);
    dim3 grid(T_LEN / BM, NQ_H, B);
    attn_fwd_mma<<<grid, NTHREADS, SMEM_TOTAL>>>(q, seg, out);
}

// round 11
// speedup vs baseline: 1.1141x; 1.1141x over previous
#include <cuda_runtime.h>
#include <cuda_bf16.h>
#include <cstdint>

#define T_LEN    2048
#define D_DIM    128
#define NQ_H     32
#define NKV_H    8
#define B_MAX    2
#define BM       64
#define BN       64
#define NTHREADS 128
#define LOG2E    1.4426950408889634f

// smem (bytes): bf16 tiles, row stride 272B -> conflict-free ldmatrix
#define ROWB     272
#define SUBSZ    17408
#define OFF_QHI  0
#define OFF_QLO  17408
#define OFF_KV   34816          // KHI,KLO,VHI,VLO x 17408
#define OFF_SEG  104448         // 64 ints
#define SMEM_TOTAL 104704

// pre-split K/V scratch (bf16 hi/lo), layout [b][kvh][t][d]
#define KV_ELEMS (B_MAX * NKV_H * T_LEN * D_DIM)
__device__ __nv_bfloat16 g_khi[KV_ELEMS];
__device__ __nv_bfloat16 g_klo[KV_ELEMS];
__device__ __nv_bfloat16 g_vhi[KV_ELEMS];
__device__ __nv_bfloat16 g_vlo[KV_ELEMS];

__device__ __forceinline__ uint32_t smem_u32(const void* p) {
    uint32_t a;
    asm("{ .reg .u64 t; cvta.to.shared.u64 t, %1; cvt.u32.u64 %0, t; }" : "=r"(a) : "l"(p));
    return a;
}
__device__ __forceinline__ float ex2f(float x) {
    float r;
    asm("ex2.approx.ftz.f32 %0, %1;" : "=f"(r) : "f"(x));
    return r;
}
__device__ __forceinline__ void mma16816(float* d, const uint32_t* a, const uint32_t* b) {
    asm volatile("mma.sync.aligned.m16n8k16.row.col.f32.bf16.bf16.f32 "
                 "{%0,%1,%2,%3}, {%4,%5,%6,%7}, {%8,%9}, {%0,%1,%2,%3};"
                 : "+f"(d[0]), "+f"(d[1]), "+f"(d[2]), "+f"(d[3])
                 : "r"(a[0]), "r"(a[1]), "r"(a[2]), "r"(a[3]), "r"(b[0]), "r"(b[1]));
}
__device__ __forceinline__ void ldsm_x4(uint32_t* r, uint32_t addr) {
    asm volatile("ldmatrix.sync.aligned.m8n8.x4.shared.b16 {%0,%1,%2,%3}, [%4];"
                 : "=r"(r[0]), "=r"(r[1]), "=r"(r[2]), "=r"(r[3]) : "r"(addr));
}
__device__ __forceinline__ void ldsm_x4t(uint32_t* r, uint32_t addr) {
    asm volatile("ldmatrix.sync.aligned.m8n8.x4.trans.shared.b16 {%0,%1,%2,%3}, [%4];"
                 : "=r"(r[0]), "=r"(r[1]), "=r"(r[2]), "=r"(r[3]) : "r"(addr));
}
__device__ __forceinline__ void split2(float x, float y, uint32_t& hi, uint32_t& lo) {
    __nv_bfloat162 h = __floats2bfloat162_rn(x, y);
    float hx = __low2float(h), hy = __high2float(h);
    __nv_bfloat162 l = __floats2bfloat162_rn(x - hx, y - hy);
    hi = *(uint32_t*)&h;
    lo = *(uint32_t*)&l;
}
__device__ __forceinline__ void cp16(uint32_t dst, const void* src) {
    size_t g = __cvta_generic_to_global(src);
    asm volatile("cp.async.cg.shared.global [%0], [%1], 16;" :: "r"(dst), "l"(g) : "memory");
}
#define CP_COMMIT() asm volatile("cp.async.commit_group;" ::: "memory")
#define CP_WAIT0()  asm volatile("cp.async.wait_group 0;" ::: "memory")

// ---- prep kernel: split K/V f32 -> bf16 hi/lo, relayout [b][kvh][t][d] ----
__global__ void prep_kv(const float* __restrict__ K, const float* __restrict__ V) {
    const int t = blockIdx.x, h = blockIdx.y, b = blockIdx.z;
    const int d = threadIdx.x * 2;
    const size_t src = ((size_t)(b * T_LEN + t) * NKV_H + h) * D_DIM + d;
    const size_t dst = ((size_t)(b * NKV_H + h) * T_LEN + t) * D_DIM + d;
    float2 kv = *(const float2*)(K + src);
    float2 vv = *(const float2*)(V + src);
    uint32_t hh, ll;
    split2(kv.x, kv.y, hh, ll);
    *(uint32_t*)(g_khi + dst) = hh; *(uint32_t*)(g_klo + dst) = ll;
    split2(vv.x, vv.y, hh, ll);
    *(uint32_t*)(g_vhi + dst) = hh; *(uint32_t*)(g_vlo + dst) = ll;
}

__device__ __forceinline__ void prefetch_tile(uint32_t sb, int tid, size_t kvoff, int n0,
                                              const int* __restrict__ segB) {
    const uint32_t base = sb + OFF_KV;
    const __nv_bfloat16* srcs[4] = { g_khi + kvoff, g_klo + kvoff,
                                     g_vhi + kvoff, g_vlo + kvoff };
#pragma unroll
    for (int sub = 0; sub < 4; sub++) {
        const __nv_bfloat16* sp = srcs[sub] + (size_t)n0 * D_DIM;
#pragma unroll
        for (int q = 0; q < 8; q++) {
            const int i = tid + q * NTHREADS;
            const int row = i >> 4, ch = i & 15;
            cp16(base + sub * SUBSZ + row * ROWB + ch * 16,
                 sp + row * D_DIM + ch * 8);
        }
    }
    if (tid < 16) cp16(sb + OFF_SEG + tid * 16, segB + n0 + tid * 4);
}

__global__ __launch_bounds__(NTHREADS, 2)
void attn_fwd_mma(const float* __restrict__ Q, const int* __restrict__ SEG,
                  float* __restrict__ O)
{
    extern __shared__ __align__(16) char smem[];
    const uint32_t sb = smem_u32(smem);

    const int b   = blockIdx.z;
    const int qh  = blockIdx.y;
    const int kvh = qh >> 2;
    const int m0  = ((int)gridDim.x - 1 - (int)blockIdx.x) * BM;  // heavy blocks first

    const int tid  = threadIdx.x;
    const int w    = tid >> 5;        // 0..3
    const int lane = tid & 31;
    const int g    = lane >> 2;
    const int qc   = lane & 3;

    const int* segB = SEG + b * T_LEN;
    const size_t kvoff = ((size_t)b * NKV_H + kvh) * T_LEN * D_DIM;

    // ---- load Q tile [BM x D], scale by log2e, split hi/lo ----
    const float* qbase = Q + ((size_t)(b * T_LEN + m0) * NQ_H + qh) * D_DIM;
    for (int i = tid; i < BM * (D_DIM / 4); i += NTHREADS) {
        int r = i >> 5, e = (i & 31) * 4;
        float4 qv = *(const float4*)(qbase + (size_t)r * NQ_H * D_DIM + e);
        uint32_t h0, l0, h1, l1;
        split2(qv.x * LOG2E, qv.y * LOG2E, h0, l0);
        split2(qv.z * LOG2E, qv.w * LOG2E, h1, l1);
        uint32_t off = (uint32_t)(r * ROWB + e * 2);
        *(uint32_t*)(smem + OFF_QHI + off)     = h0;
        *(uint32_t*)(smem + OFF_QHI + off + 4) = h1;
        *(uint32_t*)(smem + OFF_QLO + off)     = l0;
        *(uint32_t*)(smem + OFF_QLO + off + 4) = l1;
    }

    const int rG0 = m0 + w * 16 + g;
    const int rG1 = rG0 + 8;
    const int segRowMin = segB[m0];
    const int segRowMax = segB[m0 + BM - 1];
    const int rowSeg0 = segB[rG0];
    const int rowSeg1 = segB[rG1];

    float m0r = -1e30f, m1r = -1e30f, l0r = 0.f, l1r = 0.f;
    float o[16][4];
#pragma unroll
    for (int j = 0; j < 16; j++)
#pragma unroll
        for (int u = 0; u < 4; u++) o[j][u] = 0.f;

    // ldmatrix lane address components
    const int arow = w * 16 + (lane & 7) + ((lane >> 3) & 1) * 8;
    const uint32_t aColOff = (uint32_t)(((lane >> 4) * 8) * 2);
    const uint32_t aHiBase = sb + OFF_QHI + (uint32_t)arow * ROWB + aColOff;
    const uint32_t aLoBase = sb + OFF_QLO + (uint32_t)arow * ROWB + aColOff;
    const uint32_t bRow4 = (uint32_t)(((lane & 7) + ((lane >> 4) & 1) * 8) * ROWB
                                      + ((lane >> 3) & 1) * 16);
    const uint32_t vRow4 = (uint32_t)(((lane & 7) + ((lane >> 3) & 1) * 8) * ROWB
                                      + ((lane >> 4) & 1) * 16);

    const int nTiles = m0 / BN + 1;   // BM == BN == 64

    for (int nt = 0; nt < nTiles; nt++) {
        const int n0 = nt * BN;
        if (segB[n0] > segRowMax || segB[n0 + BN - 1] < segRowMin) continue;

        __syncthreads();   // all warps done reading previous tile
        prefetch_tile(sb, tid, kvoff, n0, segB);
        CP_COMMIT();
        CP_WAIT0();
        __syncthreads();   // tile visible to all warps

        const uint32_t bufBase = sb + OFF_KV;
        const int* segK = (const int*)(smem + OFF_SEG);

        // ---- S = Q K^T (3-term), MMAs round-robined over 8 accumulators ----
        float s[8][4];
#pragma unroll
        for (int j = 0; j < 8; j++)
#pragma unroll
            for (int u = 0; u < 4; u++) s[j][u] = 0.f;

#pragma unroll
        for (int kc = 0; kc < 8; kc++) {
            uint32_t aHi[4], aLo[4];
            ldsm_x4(aHi, aHiBase + kc * 32);
            ldsm_x4(aLo, aLoBase + kc * 32);
            uint32_t bH[16], bL[16];
#pragma unroll
            for (int jp = 0; jp < 4; jp++) {
                const uint32_t bo = bufBase + (uint32_t)(jp * 16 * ROWB) + bRow4 + kc * 32;
                ldsm_x4(bH + 4 * jp, bo);
                ldsm_x4(bL + 4 * jp, bo + SUBSZ);
            }
            // term hi*hi across all 8 accumulators
#pragma unroll
            for (int jp = 0; jp < 4; jp++) {
                mma16816(s[2*jp],   aHi, bH + 4*jp);
                mma16816(s[2*jp+1], aHi, bH + 4*jp + 2);
            }
            // term lo*hi
#pragma unroll
            for (int jp = 0; jp < 4; jp++) {
                mma16816(s[2*jp],   aLo, bH + 4*jp);
                mma16816(s[2*jp+1], aLo, bH + 4*jp + 2);
            }
            // term hi*lo
#pragma unroll
            for (int jp = 0; jp < 4; jp++) {
                mma16816(s[2*jp],   aHi, bL + 4*jp);
                mma16816(s[2*jp+1], aHi, bL + 4*jp + 2);
            }
        }

        // ---- mask + online softmax (warp-local) ----
        float mt0 = -1e30f, mt1 = -1e30f;
#pragma unroll
        for (int j = 0; j < 8; j++) {
            const int col = 8 * j + 2 * qc;
            const int c0 = n0 + col, c1 = c0 + 1;
            const int sg0 = segK[col], sg1 = segK[col + 1];
            if (!(c0 <= rG0 && sg0 == rowSeg0)) s[j][0] = -1e30f;
            if (!(c1 <= rG0 && sg1 == rowSeg0)) s[j][1] = -1e30f;
            if (!(c0 <= rG1 && sg0 == rowSeg1)) s[j][2] = -1e30f;
            if (!(c1 <= rG1 && sg1 == rowSeg1)) s[j][3] = -1e30f;
            mt0 = fmaxf(mt0, fmaxf(s[j][0], s[j][1]));
            mt1 = fmaxf(mt1, fmaxf(s[j][2], s[j][3]));
        }
        mt0 = fmaxf(mt0, __shfl_xor_sync(0xffffffffu, mt0, 1));
        mt0 = fmaxf(mt0, __shfl_xor_sync(0xffffffffu, mt0, 2));
        mt1 = fmaxf(mt1, __shfl_xor_sync(0xffffffffu, mt1, 1));
        mt1 = fmaxf(mt1, __shfl_xor_sync(0xffffffffu, mt1, 2));

        const float mn0 = fmaxf(m0r, mt0), mn1 = fmaxf(m1r, mt1);
        const float al0 = ex2f(m0r - mn0), al1 = ex2f(m1r - mn1);
        m0r = mn0; m1r = mn1;

        float ls0 = 0.f, ls1 = 0.f;
#pragma unroll
        for (int j = 0; j < 8; j++) {
            s[j][0] = ex2f(s[j][0] - mn0);
            s[j][1] = ex2f(s[j][1] - mn0);
            s[j][2] = ex2f(s[j][2] - mn1);
            s[j][3] = ex2f(s[j][3] - mn1);
            ls0 += s[j][0] + s[j][1];
            ls1 += s[j][2] + s[j][3];
        }
        ls0 += __shfl_xor_sync(0xffffffffu, ls0, 1);
        ls0 += __shfl_xor_sync(0xffffffffu, ls0, 2);
        ls1 += __shfl_xor_sync(0xffffffffu, ls1, 1);
        ls1 += __shfl_xor_sync(0xffffffffu, ls1, 2);
        l0r = l0r * al0 + ls0;
        l1r = l1r * al1 + ls1;

        // ---- rescale O (skip if alpha==1 warp-wide) ----
        if (!__all_sync(0xffffffffu, (al0 == 1.f) && (al1 == 1.f))) {
#pragma unroll
            for (int j = 0; j < 16; j++) {
                o[j][0] *= al0; o[j][1] *= al0;
                o[j][2] *= al1; o[j][3] *= al1;
            }
        }

        // ---- O += P V (3-term), RR over 8 accumulators per half ----
        const uint32_t vBase = bufBase + 2 * SUBSZ;
#pragma unroll
        for (int kc2 = 0; kc2 < 4; kc2++) {
            uint32_t pHi[4], pLo[4];
            split2(s[2*kc2][0],   s[2*kc2][1],   pHi[0], pLo[0]);
            split2(s[2*kc2][2],   s[2*kc2][3],   pHi[1], pLo[1]);
            split2(s[2*kc2+1][0], s[2*kc2+1][1], pHi[2], pLo[2]);
            split2(s[2*kc2+1][2], s[2*kc2+1][3], pHi[3], pLo[3]);
            const uint32_t vRowBase = vBase + (uint32_t)(kc2 * 16 * ROWB) + vRow4;
#pragma unroll
            for (int h = 0; h < 2; h++) {
                uint32_t vH[16], vL[16];
#pragma unroll
                for (int jq = 0; jq < 4; jq++) {
                    const uint32_t bo = vRowBase + (h * 4 + jq) * 32;
                    ldsm_x4t(vH + 4 * jq, bo);
                    ldsm_x4t(vL + 4 * jq, bo + SUBSZ);
                }
                float* oh = &o[8 * h][0];
                // term Phi*Vhi
#pragma unroll
                for (int jq = 0; jq < 4; jq++) {
                    mma16816(oh + 8*jq,     pHi, vH + 4*jq);
                    mma16816(oh + 8*jq + 4, pHi, vH + 4*jq + 2);
                }
                // term Plo*Vhi
#pragma unroll
                for (int jq = 0; jq < 4; jq++) {
                    mma16816(oh + 8*jq,     pLo, vH + 4*jq);
                    mma16816(oh + 8*jq + 4, pLo, vH + 4*jq + 2);
                }
                // term Phi*Vlo
#pragma unroll
                for (int jq = 0; jq < 4; jq++) {
                    mma16816(oh + 8*jq,     pHi, vL + 4*jq);
                    mma16816(oh + 8*jq + 4, pHi, vL + 4*jq + 2);
                }
            }
        }
    }

    // ---- epilogue ----
    {
        const float i0 = 1.0f / l0r, i1 = 1.0f / l1r;
        float* ob0 = O + ((size_t)(b * T_LEN + rG0) * NQ_H + qh) * D_DIM;
        float* ob1 = O + ((size_t)(b * T_LEN + rG1) * NQ_H + qh) * D_DIM;
#pragma unroll
        for (int j2 = 0; j2 < 16; j2++) {
            const int col = 8 * j2 + 2 * qc;
            *(float2*)(ob0 + col) = make_float2(o[j2][0] * i0, o[j2][1] * i0);
            *(float2*)(ob1 + col) = make_float2(o[j2][2] * i1, o[j2][3] * i1);
        }
    }
}

extern "C" void kernel_launch(void* const* d_in, const int* in_sizes, int n_in,
                              void* d_out, int out_size)
{
    const float* q   = (const float*)d_in[0];
    const float* k   = (const float*)d_in[1];
    const float* v   = (const float*)d_in[2];
    const int*   seg = (const int*)d_in[3];
    float*       out = (float*)d_out;

    const int B = in_sizes[0] / (T_LEN * NQ_H * D_DIM);

    dim3 pgrid(T_LEN, NKV_H, B);
    prep_kv<<<pgrid, 64>>>(k, v);

    cudaFuncSetAttribute(attn_fwd_mma, cudaFuncAttributeMaxDynamicSharedMemorySize, SMEM_TOTAL);
    dim3 grid(T_LEN / BM, NQ_H, B);
    attn_fwd_mma<<<grid, NTHREADS, SMEM_TOTAL>>>(q, seg, out);
}

// round 13
// speedup vs baseline: 1.2349x; 1.1084x over previous
#include <cuda_runtime.h>
#include <cuda_fp16.h>
#include <cstdint>

#define T_LEN    2048
#define D_DIM    128
#define NQ_H     32
#define NKV_H    8
#define B_MAX    2
#define BM       64
#define BN       64
#define NTHREADS 128
#define LOG2E    1.4426950408889634f

// smem (bytes): fp16 tiles, row stride 272B -> conflict-free ldmatrix
#define ROWB     272
#define SUBSZ    17408
#define OFF_QHI  0
#define OFF_QLO  17408
#define OFF_K    34816          // KHI, KLO  (single buffer)
#define OFF_V    69632          // VHI x 2 buffers
#define OFF_SEG  104448         // 2 x 256 B
#define SMEM_TOTAL 104960

// pre-split K/V scratch (fp16), layout [b][kvh][t][d]
#define KV_ELEMS (B_MAX * NKV_H * T_LEN * D_DIM)
__device__ __half g_khi[KV_ELEMS];
__device__ __half g_klo[KV_ELEMS];
__device__ __half g_vhi[KV_ELEMS];

__device__ __forceinline__ uint32_t smem_u32(const void* p) {
    uint32_t a;
    asm("{ .reg .u64 t; cvta.to.shared.u64 t, %1; cvt.u32.u64 %0, t; }" : "=r"(a) : "l"(p));
    return a;
}
__device__ __forceinline__ float ex2f(float x) {
    float r;
    asm("ex2.approx.ftz.f32 %0, %1;" : "=f"(r) : "f"(x));
    return r;
}
__device__ __forceinline__ void mma16816(float* d, const uint32_t* a, const uint32_t* b) {
    asm volatile("mma.sync.aligned.m16n8k16.row.col.f32.f16.f16.f32 "
                 "{%0,%1,%2,%3}, {%4,%5,%6,%7}, {%8,%9}, {%0,%1,%2,%3};"
                 : "+f"(d[0]), "+f"(d[1]), "+f"(d[2]), "+f"(d[3])
                 : "r"(a[0]), "r"(a[1]), "r"(a[2]), "r"(a[3]), "r"(b[0]), "r"(b[1]));
}
__device__ __forceinline__ void ldsm_x4(uint32_t* r, uint32_t addr) {
    asm volatile("ldmatrix.sync.aligned.m8n8.x4.shared.b16 {%0,%1,%2,%3}, [%4];"
                 : "=r"(r[0]), "=r"(r[1]), "=r"(r[2]), "=r"(r[3]) : "r"(addr));
}
__device__ __forceinline__ void ldsm_x4t(uint32_t* r, uint32_t addr) {
    asm volatile("ldmatrix.sync.aligned.m8n8.x4.trans.shared.b16 {%0,%1,%2,%3}, [%4];"
                 : "=r"(r[0]), "=r"(r[1]), "=r"(r[2]), "=r"(r[3]) : "r"(addr));
}
// split x,y into packed fp16x2 hi and lo
__device__ __forceinline__ void split2h(float x, float y, uint32_t& hi, uint32_t& lo) {
    __half2 h = __floats2half2_rn(x, y);
    float hx = __low2float(h), hy = __high2float(h);
    __half2 l = __floats2half2_rn(x - hx, y - hy);
    hi = *(uint32_t*)&h;
    lo = *(uint32_t*)&l;
}
__device__ __forceinline__ void cp16(uint32_t dst, const void* src) {
    size_t g = __cvta_generic_to_global(src);
    asm volatile("cp.async.cg.shared.global [%0], [%1], 16;" :: "r"(dst), "l"(g) : "memory");
}
#define CP_COMMIT() asm volatile("cp.async.commit_group;" ::: "memory")
#define CP_WAIT0()  asm volatile("cp.async.wait_group 0;" ::: "memory")
#define CP_WAIT1()  asm volatile("cp.async.wait_group 1;" ::: "memory")

// ---- prep kernel: K -> fp16 hi/lo, V -> fp16 hi; relayout [b][kvh][t][d] ----
__global__ void prep_kv(const float* __restrict__ K, const float* __restrict__ V) {
    const int t = blockIdx.x, h = blockIdx.y, b = blockIdx.z;
    const int d = threadIdx.x * 2;
    const size_t src = ((size_t)(b * T_LEN + t) * NKV_H + h) * D_DIM + d;
    const size_t dst = ((size_t)(b * NKV_H + h) * T_LEN + t) * D_DIM + d;
    float2 kv = *(const float2*)(K + src);
    float2 vv = *(const float2*)(V + src);
    uint32_t hh, ll;
    split2h(kv.x, kv.y, hh, ll);
    *(uint32_t*)(g_khi + dst) = hh; *(uint32_t*)(g_klo + dst) = ll;
    __half2 vh = __floats2half2_rn(vv.x, vv.y);
    *(uint32_t*)(g_vhi + dst) = *(uint32_t*)&vh;
}

// K (hi+lo) + seg -> fixed K buffer, seg slot by parity
__device__ __forceinline__ void prefetch_K(uint32_t sb, int slot, int tid,
                                           size_t kvoff, int n0,
                                           const int* __restrict__ segB) {
    const __half* srcs[2] = { g_khi + kvoff, g_klo + kvoff };
#pragma unroll
    for (int sub = 0; sub < 2; sub++) {
        const __half* sp = srcs[sub] + (size_t)n0 * D_DIM;
#pragma unroll
        for (int q = 0; q < 8; q++) {
            const int i = tid + q * NTHREADS;
            const int row = i >> 4, ch = i & 15;
            cp16(sb + OFF_K + sub * SUBSZ + row * ROWB + ch * 16,
                 sp + row * D_DIM + ch * 8);
        }
    }
    if (tid < 16) cp16(sb + OFF_SEG + slot * 256 + tid * 16, segB + n0 + tid * 4);
}
// V (hi) -> V buffer [slot]
__device__ __forceinline__ void prefetch_V(uint32_t sb, int slot, int tid,
                                           size_t kvoff, int n0) {
    const __half* sp = g_vhi + kvoff + (size_t)n0 * D_DIM;
#pragma unroll
    for (int q = 0; q < 8; q++) {
        const int i = tid + q * NTHREADS;
        const int row = i >> 4, ch = i & 15;
        cp16(sb + OFF_V + slot * SUBSZ + row * ROWB + ch * 16,
             sp + row * D_DIM + ch * 8);
    }
}

__global__ __launch_bounds__(NTHREADS, 2)
void attn_fwd_mma(const float* __restrict__ Q, const int* __restrict__ SEG,
                  float* __restrict__ O)
{
    extern __shared__ __align__(16) char smem[];
    const uint32_t sb = smem_u32(smem);

    const int b   = blockIdx.z;
    const int qh  = blockIdx.y;
    const int kvh = qh >> 2;
    const int m0  = ((int)gridDim.x - 1 - (int)blockIdx.x) * BM;  // heavy blocks first

    const int tid  = threadIdx.x;
    const int w    = tid >> 5;        // 0..3
    const int lane = tid & 31;
    const int g    = lane >> 2;
    const int qc   = lane & 3;

    const int* segB = SEG + b * T_LEN;
    const size_t kvoff = ((size_t)b * NKV_H + kvh) * T_LEN * D_DIM;

    const int segRowMin = segB[m0];
    const int segRowMax = segB[m0 + BM - 1];
    const int nTiles = m0 / BN + 1;   // BM == BN == 64

    // ---- find first valid tile, start K+V prefetch before Q work ----
    int ntCur = -1;
    for (int t = 0; t < nTiles; t++) {
        if (!(segB[t * BN] > segRowMax || segB[t * BN + BN - 1] < segRowMin)) { ntCur = t; break; }
    }
    int vb = 0;
    if (ntCur >= 0) {
        prefetch_K(sb, vb, tid, kvoff, ntCur * BN, segB); CP_COMMIT();
        prefetch_V(sb, vb, tid, kvoff, ntCur * BN);       CP_COMMIT();
    }

    // ---- load Q tile [BM x D], scale by log2e, split fp16 hi/lo ----
    const float* qbase = Q + ((size_t)(b * T_LEN + m0) * NQ_H + qh) * D_DIM;
    for (int i = tid; i < BM * (D_DIM / 4); i += NTHREADS) {
        int r = i >> 5, e = (i & 31) * 4;
        float4 qv = *(const float4*)(qbase + (size_t)r * NQ_H * D_DIM + e);
        uint32_t h0, l0, h1, l1;
        split2h(qv.x * LOG2E, qv.y * LOG2E, h0, l0);
        split2h(qv.z * LOG2E, qv.w * LOG2E, h1, l1);
        uint32_t off = (uint32_t)(r * ROWB + e * 2);
        *(uint32_t*)(smem + OFF_QHI + off)     = h0;
        *(uint32_t*)(smem + OFF_QHI + off + 4) = h1;
        *(uint32_t*)(smem + OFF_QLO + off)     = l0;
        *(uint32_t*)(smem + OFF_QLO + off + 4) = l1;
    }

    const int rG0 = m0 + w * 16 + g;
    const int rG1 = rG0 + 8;
    const int rowSeg0 = segB[rG0];
    const int rowSeg1 = segB[rG1];

    float m0r = -1e30f, m1r = -1e30f, l0r = 0.f, l1r = 0.f;
    float o[16][4];
#pragma unroll
    for (int j = 0; j < 16; j++)
#pragma unroll
        for (int u = 0; u < 4; u++) o[j][u] = 0.f;

    // ldmatrix lane address components
    const int arow = w * 16 + (lane & 7) + ((lane >> 3) & 1) * 8;
    const uint32_t aColOff = (uint32_t)(((lane >> 4) * 8) * 2);
    const uint32_t aHiBase = sb + OFF_QHI + (uint32_t)arow * ROWB + aColOff;
    const uint32_t aLoBase = sb + OFF_QLO + (uint32_t)arow * ROWB + aColOff;
    const uint32_t bRow4 = (uint32_t)(((lane & 7) + ((lane >> 4) & 1) * 8) * ROWB
                                      + ((lane >> 3) & 1) * 16);
    const uint32_t vRow4 = (uint32_t)(((lane & 7) + ((lane >> 3) & 1) * 8) * ROWB
                                      + ((lane >> 4) & 1) * 16);

    while (ntCur >= 0) {
        int ntNext = -1;
        for (int t = ntCur + 1; t < nTiles; t++) {
            if (!(segB[t * BN] > segRowMax || segB[t * BN + BN - 1] < segRowMin)) { ntNext = t; break; }
        }
        const int n0 = ntCur * BN;

        CP_WAIT1();          // K(+seg) of current tile ready; V may still be in flight
        __syncthreads();

        // ---- S = Q K^T (3-term fp16), MMAs RR over 8 accumulators ----
        float s[8][4];
#pragma unroll
        for (int j = 0; j < 8; j++)
#pragma unroll
            for (int u = 0; u < 4; u++) s[j][u] = 0.f;

#pragma unroll
        for (int kc = 0; kc < 8; kc++) {
            uint32_t aHi[4], aLo[4];
            ldsm_x4(aHi, aHiBase + kc * 32);
            ldsm_x4(aLo, aLoBase + kc * 32);
            uint32_t bH[16], bL[16];
#pragma unroll
            for (int jp = 0; jp < 4; jp++) {
                const uint32_t bo = sb + OFF_K + (uint32_t)(jp * 16 * ROWB) + bRow4 + kc * 32;
                ldsm_x4(bH + 4 * jp, bo);
                ldsm_x4(bL + 4 * jp, bo + SUBSZ);
            }
#pragma unroll
            for (int jp = 0; jp < 4; jp++) {
                mma16816(s[2*jp],   aHi, bH + 4*jp);
                mma16816(s[2*jp+1], aHi, bH + 4*jp + 2);
            }
#pragma unroll
            for (int jp = 0; jp < 4; jp++) {
                mma16816(s[2*jp],   aLo, bH + 4*jp);
                mma16816(s[2*jp+1], aLo, bH + 4*jp + 2);
            }
#pragma unroll
            for (int jp = 0; jp < 4; jp++) {
                mma16816(s[2*jp],   aHi, bL + 4*jp);
                mma16816(s[2*jp+1], aHi, bL + 4*jp + 2);
            }
        }

        __syncthreads();     // all warps done reading K buffer
        if (ntNext >= 0) { prefetch_K(sb, vb ^ 1, tid, kvoff, ntNext * BN, segB); CP_COMMIT(); }

        const int* segK = (const int*)(smem + OFF_SEG + vb * 256);

        // ---- mask + online softmax (warp-local) ----
        float mt0 = -1e30f, mt1 = -1e30f;
#pragma unroll
        for (int j = 0; j < 8; j++) {
            const int col = 8 * j + 2 * qc;
            const int c0 = n0 + col, c1 = c0 + 1;
            const int sg0 = segK[col], sg1 = segK[col + 1];
            if (!(c0 <= rG0 && sg0 == rowSeg0)) s[j][0] = -1e30f;
            if (!(c1 <= rG0 && sg1 == rowSeg0)) s[j][1] = -1e30f;
            if (!(c0 <= rG1 && sg0 == rowSeg1)) s[j][2] = -1e30f;
            if (!(c1 <= rG1 && sg1 == rowSeg1)) s[j][3] = -1e30f;
            mt0 = fmaxf(mt0, fmaxf(s[j][0], s[j][1]));
            mt1 = fmaxf(mt1, fmaxf(s[j][2], s[j][3]));
        }
        mt0 = fmaxf(mt0, __shfl_xor_sync(0xffffffffu, mt0, 1));
        mt0 = fmaxf(mt0, __shfl_xor_sync(0xffffffffu, mt0, 2));
        mt1 = fmaxf(mt1, __shfl_xor_sync(0xffffffffu, mt1, 1));
        mt1 = fmaxf(mt1, __shfl_xor_sync(0xffffffffu, mt1, 2));

        const float mn0 = fmaxf(m0r, mt0), mn1 = fmaxf(m1r, mt1);
        const float al0 = ex2f(m0r - mn0), al1 = ex2f(m1r - mn1);
        m0r = mn0; m1r = mn1;

        float ls0 = 0.f, ls1 = 0.f;
#pragma unroll
        for (int j = 0; j < 8; j++) {
            s[j][0] = ex2f(s[j][0] - mn0);
            s[j][1] = ex2f(s[j][1] - mn0);
            s[j][2] = ex2f(s[j][2] - mn1);
            s[j][3] = ex2f(s[j][3] - mn1);
            ls0 += s[j][0] + s[j][1];
            ls1 += s[j][2] + s[j][3];
        }
        ls0 += __shfl_xor_sync(0xffffffffu, ls0, 1);
        ls0 += __shfl_xor_sync(0xffffffffu, ls0, 2);
        ls1 += __shfl_xor_sync(0xffffffffu, ls1, 1);
        ls1 += __shfl_xor_sync(0xffffffffu, ls1, 2);
        l0r = l0r * al0 + ls0;
        l1r = l1r * al1 + ls1;

        // ---- rescale O (skip if alpha==1 warp-wide) ----
        if (!__all_sync(0xffffffffu, (al0 == 1.f) && (al1 == 1.f))) {
#pragma unroll
            for (int j = 0; j < 16; j++) {
                o[j][0] *= al0; o[j][1] *= al0;
                o[j][2] *= al1; o[j][3] *= al1;
            }
        }

        // ---- wait for V of current tile, then O += (Phi+Plo) Vhi ----
        if (ntNext >= 0) { CP_WAIT1(); } else { CP_WAIT0(); }
        __syncthreads();     // V visible to all warps

        const uint32_t vBase = sb + OFF_V + vb * SUBSZ;
#pragma unroll
        for (int kc2 = 0; kc2 < 4; kc2++) {
            uint32_t pHi[4], pLo[4];
            split2h(s[2*kc2][0],   s[2*kc2][1],   pHi[0], pLo[0]);
            split2h(s[2*kc2][2],   s[2*kc2][3],   pHi[1], pLo[1]);
            split2h(s[2*kc2+1][0], s[2*kc2+1][1], pHi[2], pLo[2]);
            split2h(s[2*kc2+1][2], s[2*kc2+1][3], pHi[3], pLo[3]);
            const uint32_t vRowBase = vBase + (uint32_t)(kc2 * 16 * ROWB) + vRow4;
#pragma unroll
            for (int h = 0; h < 2; h++) {
                uint32_t vH[16];
#pragma unroll
                for (int jq = 0; jq < 4; jq++)
                    ldsm_x4t(vH + 4 * jq, vRowBase + (h * 4 + jq) * 32);
                float* oh = &o[8 * h][0];
#pragma unroll
                for (int jq = 0; jq < 4; jq++) {
                    mma16816(oh + 8*jq,     pHi, vH + 4*jq);
                    mma16816(oh + 8*jq + 4, pHi, vH + 4*jq + 2);
                }
#pragma unroll
                for (int jq = 0; jq < 4; jq++) {
                    mma16816(oh + 8*jq,     pLo, vH + 4*jq);
                    mma16816(oh + 8*jq + 4, pLo, vH + 4*jq + 2);
                }
            }
        }

        // prefetch next V into the other buffer (no barrier needed: different buffer,
        // last reader of vb^1 finished before this tile's earlier syncs)
        if (ntNext >= 0) { prefetch_V(sb, vb ^ 1, tid, kvoff, ntNext * BN); CP_COMMIT(); }

        vb ^= 1;
        ntCur = ntNext;
    }

    // ---- epilogue ----
    {
        const float i0 = 1.0f / l0r, i1 = 1.0f / l1r;
        float* ob0 = O + ((size_t)(b * T_LEN + rG0) * NQ_H + qh) * D_DIM;
        float* ob1 = O + ((size_t)(b * T_LEN + rG1) * NQ_H + qh) * D_DIM;
#pragma unroll
        for (int j2 = 0; j2 < 16; j2++) {
            const int col = 8 * j2 + 2 * qc;
            *(float2*)(ob0 + col) = make_float2(o[j2][0] * i0, o[j2][1] * i0);
            *(float2*)(ob1 + col) = make_float2(o[j2][2] * i1, o[j2][3] * i1);
        }
    }
}

extern "C" void kernel_launch(void* const* d_in, const int* in_sizes, int n_in,
                              void* d_out, int out_size)
{
    const float* q   = (const float*)d_in[0];
    const float* k   = (const float*)d_in[1];
    const float* v   = (const float*)d_in[2];
    const int*   seg = (const int*)d_in[3];
    float*       out = (float*)d_out;

    const int B = in_sizes[0] / (T_LEN * NQ_H * D_DIM);

    dim3 pgrid(T_LEN, NKV_H, B);
    prep_kv<<<pgrid, 64>>>(k, v);

    cudaFuncSetAttribute(attn_fwd_mma, cudaFuncAttributeMaxDynamicSharedMemorySize, SMEM_TOTAL);
    dim3 grid(T_LEN / BM, NQ_H, B);
    attn_fwd_mma<<<grid, NTHREADS, SMEM_TOTAL>>>(q, seg, out);
}

// round 14
// speedup vs baseline: 1.4140x; 1.1451x over previous
#include <cuda_runtime.h>
#include <cuda_fp16.h>
#include <cstdint>

#define T_LEN    2048
#define D_DIM    128
#define NQ_H     32
#define NKV_H    8
#define B_MAX    2
#define BM       64
#define BN       64
#define NTHREADS 128
#define LOG2E    1.4426950408889634f

// smem (bytes): fp16 tiles, row stride 272B -> conflict-free ldmatrix
#define ROWB     272
#define SUBSZ    17408
#define OFF_QHI  0
#define OFF_QLO  17408
#define OFF_K    34816          // KHI, KLO (single buffer)
#define OFF_V    69632          // VHI x 2 buffers
#define SMEM_TOTAL 104448

// pre-split K/V scratch (fp16), layout [b][kvh][t][d]
#define KV_ELEMS (B_MAX * NKV_H * T_LEN * D_DIM)
__device__ __half g_khi[KV_ELEMS];
__device__ __half g_klo[KV_ELEMS];
__device__ __half g_vhi[KV_ELEMS];

__device__ __forceinline__ uint32_t smem_u32(const void* p) {
    uint32_t a;
    asm("{ .reg .u64 t; cvta.to.shared.u64 t, %1; cvt.u32.u64 %0, t; }" : "=r"(a) : "l"(p));
    return a;
}
__device__ __forceinline__ float ex2f(float x) {
    float r;
    asm("ex2.approx.ftz.f32 %0, %1;" : "=f"(r) : "f"(x));
    return r;
}
__device__ __forceinline__ void mma16816(float* d, const uint32_t* a, const uint32_t* b) {
    asm volatile("mma.sync.aligned.m16n8k16.row.col.f32.f16.f16.f32 "
                 "{%0,%1,%2,%3}, {%4,%5,%6,%7}, {%8,%9}, {%0,%1,%2,%3};"
                 : "+f"(d[0]), "+f"(d[1]), "+f"(d[2]), "+f"(d[3])
                 : "r"(a[0]), "r"(a[1]), "r"(a[2]), "r"(a[3]), "r"(b[0]), "r"(b[1]));
}
__device__ __forceinline__ void ldsm_x4(uint32_t* r, uint32_t addr) {
    asm volatile("ldmatrix.sync.aligned.m8n8.x4.shared.b16 {%0,%1,%2,%3}, [%4];"
                 : "=r"(r[0]), "=r"(r[1]), "=r"(r[2]), "=r"(r[3]) : "r"(addr));
}
__device__ __forceinline__ void ldsm_x4t(uint32_t* r, uint32_t addr) {
    asm volatile("ldmatrix.sync.aligned.m8n8.x4.trans.shared.b16 {%0,%1,%2,%3}, [%4];"
                 : "=r"(r[0]), "=r"(r[1]), "=r"(r[2]), "=r"(r[3]) : "r"(addr));
}
__device__ __forceinline__ void split2h(float x, float y, uint32_t& hi, uint32_t& lo) {
    __half2 h = __floats2half2_rn(x, y);
    float hx = __low2float(h), hy = __high2float(h);
    __half2 l = __floats2half2_rn(x - hx, y - hy);
    hi = *(uint32_t*)&h;
    lo = *(uint32_t*)&l;
}
__device__ __forceinline__ uint32_t pack_h2(float x, float y) {
    __half2 h = __floats2half2_rn(x, y);
    return *(uint32_t*)&h;
}
__device__ __forceinline__ void cp16(uint32_t dst, const void* src) {
    size_t g = __cvta_generic_to_global(src);
    asm volatile("cp.async.cg.shared.global [%0], [%1], 16;" :: "r"(dst), "l"(g) : "memory");
}
#define CP_COMMIT() asm volatile("cp.async.commit_group;" ::: "memory")
#define CP_WAIT0()  asm volatile("cp.async.wait_group 0;" ::: "memory")
#define CP_WAIT1()  asm volatile("cp.async.wait_group 1;" ::: "memory")

// first index in [0, hi] with segB[idx] == val (caller guarantees segB[hi] == val)
__device__ __forceinline__ int seg_first(const int* __restrict__ segB, int val, int hi) {
    int lo = 0;
    while (lo < hi) {
        int mid = (lo + hi) >> 1;
        if (segB[mid] < val) lo = mid + 1; else hi = mid;
    }
    return lo;
}

// ---- prep kernel: K -> fp16 hi/lo, V -> fp16 hi; relayout [b][kvh][t][d] ----
__global__ void prep_kv(const float* __restrict__ K, const float* __restrict__ V) {
    const int t = blockIdx.x, h = blockIdx.y, b = blockIdx.z;
    const int d = threadIdx.x * 2;
    const size_t src = ((size_t)(b * T_LEN + t) * NKV_H + h) * D_DIM + d;
    const size_t dst = ((size_t)(b * NKV_H + h) * T_LEN + t) * D_DIM + d;
    float2 kv = *(const float2*)(K + src);
    float2 vv = *(const float2*)(V + src);
    uint32_t hh, ll;
    split2h(kv.x, kv.y, hh, ll);
    *(uint32_t*)(g_khi + dst) = hh; *(uint32_t*)(g_klo + dst) = ll;
    *(uint32_t*)(g_vhi + dst) = pack_h2(vv.x, vv.y);
}

__device__ __forceinline__ void prefetch_K(uint32_t sb, int tid, size_t kvoff, int n0) {
    const __half* srcs[2] = { g_khi + kvoff, g_klo + kvoff };
#pragma unroll
    for (int sub = 0; sub < 2; sub++) {
        const __half* sp = srcs[sub] + (size_t)n0 * D_DIM;
#pragma unroll
        for (int q = 0; q < 8; q++) {
            const int i = tid + q * NTHREADS;
            const int row = i >> 4, ch = i & 15;
            cp16(sb + OFF_K + sub * SUBSZ + row * ROWB + ch * 16,
                 sp + row * D_DIM + ch * 8);
        }
    }
}
__device__ __forceinline__ void prefetch_V(uint32_t sb, int slot, int tid,
                                           size_t kvoff, int n0) {
    const __half* sp = g_vhi + kvoff + (size_t)n0 * D_DIM;
#pragma unroll
    for (int q = 0; q < 8; q++) {
        const int i = tid + q * NTHREADS;
        const int row = i >> 4, ch = i & 15;
        cp16(sb + OFF_V + slot * SUBSZ + row * ROWB + ch * 16,
             sp + row * D_DIM + ch * 8);
    }
}

__global__ __launch_bounds__(NTHREADS, 2)
void attn_fwd_mma(const float* __restrict__ Q, const int* __restrict__ SEG,
                  float* __restrict__ O)
{
    extern __shared__ __align__(16) char smem[];
    const uint32_t sb = smem_u32(smem);

    const int b   = blockIdx.z;
    const int qh  = blockIdx.y;
    const int kvh = qh >> 2;
    const int m0  = ((int)gridDim.x - 1 - (int)blockIdx.x) * BM;  // heavy blocks first

    const int tid  = threadIdx.x;
    const int w    = tid >> 5;        // 0..3
    const int lane = tid & 31;
    const int g    = lane >> 2;
    const int qc   = lane & 3;

    const int* segB = SEG + b * T_LEN;
    const size_t kvoff = ((size_t)b * NKV_H + kvh) * T_LEN * D_DIM;

    // ---- contiguous valid tile range (segments sorted+contiguous) ----
    const int ntStart = seg_first(segB, segB[m0], m0) / BN;
    const int ntEnd   = m0 / BN;                     // diag tile (BM == BN)

    int vb = 0;
    prefetch_K(sb, tid, kvoff, ntStart * BN); CP_COMMIT();
    prefetch_V(sb, vb, tid, kvoff, ntStart * BN); CP_COMMIT();

    // ---- load Q tile [BM x D], scale by log2e, split fp16 hi/lo ----
    const float* qbase = Q + ((size_t)(b * T_LEN + m0) * NQ_H + qh) * D_DIM;
    for (int i = tid; i < BM * (D_DIM / 4); i += NTHREADS) {
        int r = i >> 5, e = (i & 31) * 4;
        float4 qv = *(const float4*)(qbase + (size_t)r * NQ_H * D_DIM + e);
        uint32_t h0, l0, h1, l1;
        split2h(qv.x * LOG2E, qv.y * LOG2E, h0, l0);
        split2h(qv.z * LOG2E, qv.w * LOG2E, h1, l1);
        uint32_t off = (uint32_t)(r * ROWB + e * 2);
        *(uint32_t*)(smem + OFF_QHI + off)     = h0;
        *(uint32_t*)(smem + OFF_QHI + off + 4) = h1;
        *(uint32_t*)(smem + OFF_QLO + off)     = l0;
        *(uint32_t*)(smem + OFF_QLO + off + 4) = l1;
    }

    const int rG0 = m0 + w * 16 + g;
    const int rG1 = rG0 + 8;
    // per-row valid-column lower bounds (first index of the row's segment)
    const int loB0 = seg_first(segB, segB[rG0], rG0);
    const int loB1 = seg_first(segB, segB[rG1], rG1);

    float m0r = -1e30f, m1r = -1e30f, l0r = 0.f, l1r = 0.f;
    float o[16][4];
#pragma unroll
    for (int j = 0; j < 16; j++)
#pragma unroll
        for (int u = 0; u < 4; u++) o[j][u] = 0.f;

    // ldmatrix lane address components
    const int arow = w * 16 + (lane & 7) + ((lane >> 3) & 1) * 8;
    const uint32_t aColOff = (uint32_t)(((lane >> 4) * 8) * 2);
    const uint32_t aHiBase = sb + OFF_QHI + (uint32_t)arow * ROWB + aColOff;
    const uint32_t aLoBase = sb + OFF_QLO + (uint32_t)arow * ROWB + aColOff;
    const uint32_t bRow4 = (uint32_t)(((lane & 7) + ((lane >> 4) & 1) * 8) * ROWB
                                      + ((lane >> 3) & 1) * 16);
    const uint32_t vRow4 = (uint32_t)(((lane & 7) + ((lane >> 3) & 1) * 8) * ROWB
                                      + ((lane >> 4) & 1) * 16);

    for (int nt = ntStart; nt <= ntEnd; nt++) {
        const int n0 = nt * BN;
        const bool hasNext = nt < ntEnd;

        CP_WAIT1();          // K of current tile ready; V may still be in flight
        __syncthreads();

        // ---- S = Q K^T (3-term fp16), MMAs RR over 8 accumulators ----
        float s[8][4];
#pragma unroll
        for (int j = 0; j < 8; j++)
#pragma unroll
            for (int u = 0; u < 4; u++) s[j][u] = 0.f;

#pragma unroll
        for (int kc = 0; kc < 8; kc++) {
            uint32_t aHi[4], aLo[4];
            ldsm_x4(aHi, aHiBase + kc * 32);
            ldsm_x4(aLo, aLoBase + kc * 32);
            uint32_t bH[16], bL[16];
#pragma unroll
            for (int jp = 0; jp < 4; jp++) {
                const uint32_t bo = sb + OFF_K + (uint32_t)(jp * 16 * ROWB) + bRow4 + kc * 32;
                ldsm_x4(bH + 4 * jp, bo);
                ldsm_x4(bL + 4 * jp, bo + SUBSZ);
            }
#pragma unroll
            for (int jp = 0; jp < 4; jp++) {
                mma16816(s[2*jp],   aHi, bH + 4*jp);
                mma16816(s[2*jp+1], aHi, bH + 4*jp + 2);
            }
#pragma unroll
            for (int jp = 0; jp < 4; jp++) {
                mma16816(s[2*jp],   aLo, bH + 4*jp);
                mma16816(s[2*jp+1], aLo, bH + 4*jp + 2);
            }
#pragma unroll
            for (int jp = 0; jp < 4; jp++) {
                mma16816(s[2*jp],   aHi, bL + 4*jp);
                mma16816(s[2*jp+1], aHi, bL + 4*jp + 2);
            }
        }

        __syncthreads();     // all warps done reading K buffer
        if (hasNext) { prefetch_K(sb, tid, kvoff, n0 + BN); CP_COMMIT(); }

        // ---- mask (interval compare) + online softmax (warp-local) ----
        float mt0 = -1e30f, mt1 = -1e30f;
#pragma unroll
        for (int j = 0; j < 8; j++) {
            const int c0 = n0 + 8 * j + 2 * qc, c1 = c0 + 1;
            if (!(c0 >= loB0 && c0 <= rG0)) s[j][0] = -1e30f;
            if (!(c1 >= loB0 && c1 <= rG0)) s[j][1] = -1e30f;
            if (!(c0 >= loB1 && c0 <= rG1)) s[j][2] = -1e30f;
            if (!(c1 >= loB1 && c1 <= rG1)) s[j][3] = -1e30f;
            mt0 = fmaxf(mt0, fmaxf(s[j][0], s[j][1]));
            mt1 = fmaxf(mt1, fmaxf(s[j][2], s[j][3]));
        }
        mt0 = fmaxf(mt0, __shfl_xor_sync(0xffffffffu, mt0, 1));
        mt0 = fmaxf(mt0, __shfl_xor_sync(0xffffffffu, mt0, 2));
        mt1 = fmaxf(mt1, __shfl_xor_sync(0xffffffffu, mt1, 1));
        mt1 = fmaxf(mt1, __shfl_xor_sync(0xffffffffu, mt1, 2));

        const float mn0 = fmaxf(m0r, mt0), mn1 = fmaxf(m1r, mt1);
        const float al0 = ex2f(m0r - mn0), al1 = ex2f(m1r - mn1);
        m0r = mn0; m1r = mn1;

        float ls0 = 0.f, ls1 = 0.f;
#pragma unroll
        for (int j = 0; j < 8; j++) {
            s[j][0] = ex2f(s[j][0] - mn0);
            s[j][1] = ex2f(s[j][1] - mn0);
            s[j][2] = ex2f(s[j][2] - mn1);
            s[j][3] = ex2f(s[j][3] - mn1);
            ls0 += s[j][0] + s[j][1];
            ls1 += s[j][2] + s[j][3];
        }
        ls0 += __shfl_xor_sync(0xffffffffu, ls0, 1);
        ls0 += __shfl_xor_sync(0xffffffffu, ls0, 2);
        ls1 += __shfl_xor_sync(0xffffffffu, ls1, 1);
        ls1 += __shfl_xor_sync(0xffffffffu, ls1, 2);
        l0r = l0r * al0 + ls0;
        l1r = l1r * al1 + ls1;

        // ---- rescale O (skip if alpha==1 warp-wide) ----
        if (!__all_sync(0xffffffffu, (al0 == 1.f) && (al1 == 1.f))) {
#pragma unroll
            for (int j = 0; j < 16; j++) {
                o[j][0] *= al0; o[j][1] *= al0;
                o[j][2] *= al1; o[j][3] *= al1;
            }
        }

        // ---- wait for V of current tile, then O += P Vhi (1-term fp16) ----
        if (hasNext) { CP_WAIT1(); } else { CP_WAIT0(); }
        __syncthreads();     // V visible to all warps

        const uint32_t vBase = sb + OFF_V + vb * SUBSZ;
#pragma unroll
        for (int kc2 = 0; kc2 < 4; kc2++) {
            uint32_t pH[4];
            pH[0] = pack_h2(s[2*kc2][0],   s[2*kc2][1]);
            pH[1] = pack_h2(s[2*kc2][2],   s[2*kc2][3]);
            pH[2] = pack_h2(s[2*kc2+1][0], s[2*kc2+1][1]);
            pH[3] = pack_h2(s[2*kc2+1][2], s[2*kc2+1][3]);
            const uint32_t vRowBase = vBase + (uint32_t)(kc2 * 16 * ROWB) + vRow4;
#pragma unroll
            for (int h = 0; h < 2; h++) {
                uint32_t vH[16];
#pragma unroll
                for (int jq = 0; jq < 4; jq++)
                    ldsm_x4t(vH + 4 * jq, vRowBase + (h * 4 + jq) * 32);
                float* oh = &o[8 * h][0];
#pragma unroll
                for (int jq = 0; jq < 4; jq++) {
                    mma16816(oh + 8*jq,     pH, vH + 4*jq);
                    mma16816(oh + 8*jq + 4, pH, vH + 4*jq + 2);
                }
            }
        }

        if (hasNext) { prefetch_V(sb, vb ^ 1, tid, kvoff, n0 + BN); CP_COMMIT(); }
        vb ^= 1;
    }

    // ---- epilogue ----
    {
        const float i0 = 1.0f / l0r, i1 = 1.0f / l1r;
        float* ob0 = O + ((size_t)(b * T_LEN + rG0) * NQ_H + qh) * D_DIM;
        float* ob1 = O + ((size_t)(b * T_LEN + rG1) * NQ_H + qh) * D_DIM;
#pragma unroll
        for (int j2 = 0; j2 < 16; j2++) {
            const int col = 8 * j2 + 2 * qc;
            *(float2*)(ob0 + col) = make_float2(o[j2][0] * i0, o[j2][1] * i0);
            *(float2*)(ob1 + col) = make_float2(o[j2][2] * i1, o[j2][3] * i1);
        }
    }
}

extern "C" void kernel_launch(void* const* d_in, const int* in_sizes, int n_in,
                              void* d_out, int out_size)
{
    const float* q   = (const float*)d_in[0];
    const float* k   = (const float*)d_in[1];
    const float* v   = (const float*)d_in[2];
    const int*   seg = (const int*)d_in[3];
    float*       out = (float*)d_out;

    const int B = in_sizes[0] / (T_LEN * NQ_H * D_DIM);

    dim3 pgrid(T_LEN, NKV_H, B);
    prep_kv<<<pgrid, 64>>>(k, v);

    cudaFuncSetAttribute(attn_fwd_mma, cudaFuncAttributeMaxDynamicSharedMemorySize, SMEM_TOTAL);
    dim3 grid(T_LEN / BM, NQ_H, B);
    attn_fwd_mma<<<grid, NTHREADS, SMEM_TOTAL>>>(q, seg, out);
}